// round 13
// baseline (speedup 1.0000x reference)
#include <cuda_runtime.h>
#include <cuda_fp16.h>
#include <stdint.h>

// INT2 symmetric quantized linear: y[32,14336] = x[32,4096] @ W^T
//   W[o][k] = fp16(v[o][k]-2) * scale[o/128][k]  (exact in fp16: v-2 in {-2,-1,0,1})
// => y[m][o] = sum_k fp16(x[m][k]*scale[g][k]) * (v[o][k]-2)   (scale folded into A)
//
// Inputs (harness dtype model {float32,int32,bfloat16}):
//   x: float32 [131072], packed: int32 [14680064] (one packed byte each), scale: float32 [458752]
//
// 112 CTAs (one group each), 512 threads = 16 warps in TWO K-split sets:
//   set s = warps 8s..8s+7 processes K in [s*2048, (s+1)*2048), 16 cols/warp.
// Independent double-buffered pipelines per set (named barriers), f32 reduction at end.

#define IN_F   4096
#define OUT_F  14336
#define GS     128
#define NGROUPS 112
#define NTHREADS 512
#define CK     256                  // K per chunk
#define CPS    8                    // chunks per set (8*256 = 2048 = half of K)

#define A_STRIDE 528                // 512B data + 16 pad
#define ABUF  (32 * A_STRIDE)       // 16896
#define PK_STRIDE 80                // 64B packed data + 16 pad
#define PKBUF (128 * PK_STRIDE)     // 10240

#define SM_SCALE 0                  // 16KB fp32 group scales
#define SM_A     16384              // 4 bufs (set,buf) of ABUF
#define SM_PKB   (16384 + 4 * ABUF) // 83968 ; 4 bufs of PKBUF
#define SM_TOTAL (SM_PKB + 4 * PKBUF) // 124928

__device__ __forceinline__ uint32_t smem_u32(const void* p) {
    uint32_t a;
    asm("{ .reg .u64 t; cvta.to.shared.u64 t, %1; cvt.u32.u64 %0, t; }" : "=r"(a) : "l"(p));
    return a;
}
__device__ __forceinline__ uint32_t hsub2u(uint32_t a, uint32_t b) {
    uint32_t d; asm("sub.rn.f16x2 %0, %1, %2;" : "=r"(d) : "r"(a), "r"(b)); return d;
}
// nib = two 2-bit weights (pre-masked). fp16x2 of (v0-2, v1-2), exact.
__device__ __forceinline__ uint32_t deq_nib(uint32_t nib) {
    uint32_t u = nib * 0x4001u, r;   // v0 at bits 0-1, v1 at bits 16-17
    asm("lop3.b32 %0, %1, %2, %3, 0xEA;" : "=r"(r)
        : "r"(u), "r"(0x00030003u), "r"(0x64006400u));   // (u & m) | fp16 bias 1024
    return hsub2u(r, 0x64026402u);   // (1024+v) - 1026 = v-2
}
// pack low bytes of 4 int32 into one word (little-endian)
__device__ __forceinline__ uint32_t pack4(uint4 q) {
    return __byte_perm(__byte_perm(q.x, q.y, 0x0040),
                       __byte_perm(q.z, q.w, 0x0040), 0x5410);
}

#define LDSM_X4(R, ADDR) \
    asm volatile("ldmatrix.sync.aligned.m8n8.x4.shared.b16 {%0,%1,%2,%3}, [%4];" \
        : "=r"((R)[0]), "=r"((R)[1]), "=r"((R)[2]), "=r"((R)[3]) : "r"(ADDR))

#define MMA16816(C, A, B0, B1) \
    asm volatile("mma.sync.aligned.m16n8k16.row.col.f32.f16.f16.f32 " \
        "{%0,%1,%2,%3}, {%4,%5,%6,%7}, {%8,%9}, {%0,%1,%2,%3};" \
        : "+f"((C)[0]), "+f"((C)[1]), "+f"((C)[2]), "+f"((C)[3]) \
        : "r"((A)[0]), "r"((A)[1]), "r"((A)[2]), "r"((A)[3]), "r"(B0), "r"(B1))

#define STS128(ADDR, R0, R1, R2, R3) \
    asm volatile("st.shared.v4.b32 [%0], {%1, %2, %3, %4};" \
        :: "r"(ADDR), "r"(R0), "r"(R1), "r"(R2), "r"(R3) : "memory")

#define LDS128U(ADDR, R0, R1, R2, R3) \
    asm volatile("ld.shared.v4.u32 {%0,%1,%2,%3}, [%4];" \
        : "=r"(R0), "=r"(R1), "=r"(R2), "=r"(R3) : "r"(ADDR))

#define LDS128F(ADDR, V) \
    asm volatile("ld.shared.v4.f32 {%0,%1,%2,%3}, [%4];" \
        : "=f"((V).x), "=f"((V).y), "=f"((V).z), "=f"((V).w) : "r"(ADDR))

#define BAR_SET() asm volatile("bar.sync %0, 256;" :: "r"(1 + set) : "memory")

__global__ void __launch_bounds__(NTHREADS, 1)
int2_linear_kernel(const float* __restrict__ x,
                   const int* __restrict__ pw,     // one packed byte per int32
                   const float* __restrict__ scale,
                   float* __restrict__ out)
{
    extern __shared__ char smem[];
    const int tid  = threadIdx.x;
    const int set  = tid >> 8;          // 0 or 1 (K-split half)
    const int stid = tid & 255;         // id within set
    const int swarp = stid >> 5;        // 0..7
    const int lane = tid & 31;
    const int g    = blockIdx.x;
    const uint32_t sbase = smem_u32(smem);

    const uint32_t aset  = sbase + SM_A   + set * 2 * ABUF;    // this set's 2 A bufs
    const uint32_t pkset = sbase + SM_PKB + set * 2 * PKBUF;   // this set's 2 pw bufs

    // ---- stage group scales: 4096 fp32 = 16KB (1024 uint4 / 512 threads) ----
    {
        const uint4* sg = reinterpret_cast<const uint4*>(scale + (size_t)g * IN_F);
        uint4* ss = reinterpret_cast<uint4*>(smem + SM_SCALE);
        ss[tid]       = sg[tid];
        ss[tid + 512] = sg[tid + 512];
    }

    // ---- per-set staging roles ----
    const int* pwg = pw + (size_t)g * GS * (IN_F / 4);   // 1024 int32 per out-row
    const int prow = stid >> 1, phalf = stid & 1;        // pw: 2 thr/row, 32 int32 each
    const int xrow = stid >> 3, xseg = stid & 7;         // x: 32 rows x 8 segs of 32

    uint4 R[8];   // pw staging regs (32 int32)
    float4 F[8];  // x staging regs (32 floats)

#define PW_LDG(CHG) do {                                                       \
    const uint4* src = reinterpret_cast<const uint4*>(                         \
        pwg + (size_t)prow * (IN_F / 4) + (CHG) * (CK / 4) + phalf * 32);      \
    _Pragma("unroll")                                                          \
    for (int u = 0; u < 8; ++u) R[u] = src[u];                                 \
} while (0)

#define PW_STS(BUF) do {                                                       \
    uint32_t base = pkset + (BUF) * PKBUF + prow * PK_STRIDE + phalf * 32;     \
    STS128(base,      pack4(R[0]), pack4(R[1]), pack4(R[2]), pack4(R[3]));     \
    STS128(base + 16, pack4(R[4]), pack4(R[5]), pack4(R[6]), pack4(R[7]));     \
} while (0)

#define X_LDG(CHG) do {                                                        \
    const float4* src = reinterpret_cast<const float4*>(                       \
        x + (size_t)xrow * IN_F + (CHG) * CK + xseg * 32);                     \
    _Pragma("unroll")                                                          \
    for (int u = 0; u < 8; ++u) F[u] = src[u];                                 \
} while (0)

#define A_STS(BUF, CHG) do {                                                   \
    uint32_t sa = sbase + SM_SCALE + (uint32_t)(((CHG) * CK + xseg * 32) * 4); \
    uint32_t xa = aset + (BUF) * ABUF + xrow * A_STRIDE + xseg * 64;           \
    _Pragma("unroll")                                                          \
    for (int i = 0; i < 4; ++i) {                                              \
        float4 s0, s1;                                                         \
        LDS128F(sa + i * 32, s0);                                              \
        LDS128F(sa + i * 32 + 16, s1);                                         \
        float4 v0 = F[2 * i], v1 = F[2 * i + 1];                               \
        __half2 h0 = __floats2half2_rn(v0.x * s0.x, v0.y * s0.y);              \
        __half2 h1 = __floats2half2_rn(v0.z * s0.z, v0.w * s0.w);              \
        __half2 h2 = __floats2half2_rn(v1.x * s1.x, v1.y * s1.y);              \
        __half2 h3 = __floats2half2_rn(v1.z * s1.z, v1.w * s1.w);              \
        STS128(xa + i * 16,                                                    \
               *reinterpret_cast<uint32_t*>(&h0),                              \
               *reinterpret_cast<uint32_t*>(&h1),                              \
               *reinterpret_cast<uint32_t*>(&h2),                              \
               *reinterpret_cast<uint32_t*>(&h3));                             \
    }                                                                          \
} while (0)

    // prologue: LDG chunk 0 of this set's K range; sync for scales; stage buf0
    const int ch0 = set * CPS;
    PW_LDG(ch0);
    X_LDG(ch0);
    __syncthreads();          // scales visible
    A_STS(0, ch0);
    PW_STS(0);
    BAR_SET();                // set's buf0 ready

    // ---- per-warp fragment addressing: warp owns cols nbase..nbase+15 ----
    const int nbase = swarp * 16;
    const int q = lane & 3;
    const uint32_t sh0 = q * 4;
    const uint32_t pkoff = (uint32_t)((nbase + (lane >> 2)) * PK_STRIDE);
    const int arow = (lane & 7) + ((lane >> 3) & 1) * 8;
    const uint32_t acol = ((lane >> 4) & 1) * 16;
    const uint32_t amoff = (uint32_t)(arow * A_STRIDE) + acol;

    float c[2][2][4] = {};    // [m-tile][n-octet][frag]

    for (int cc = 0; cc < CPS; ++cc) {
        const int cb = cc & 1, nb = cb ^ 1;
        const int chg = set * CPS + cc;

        if (cc + 1 < CPS) {   // hoist next chunk's DRAM loads under the mma loop
            PW_LDG(chg + 1);
            X_LDG(chg + 1);
        }

        const uint32_t pkb = pkset + cb * PKBUF + pkoff;
        const uint32_t am0 = aset + cb * ABUF + amoff;
        const uint32_t am1 = am0 + 16 * A_STRIDE;

#pragma unroll
        for (int j4 = 0; j4 < 4; ++j4) {
            uint32_t w0[4], w1[4];
            LDS128U(pkb + j4 * 16, w0[0], w0[1], w0[2], w0[3]);
            LDS128U(pkb + 8 * PK_STRIDE + j4 * 16, w1[0], w1[1], w1[2], w1[3]);
#pragma unroll
            for (int s = 0; s < 4; ++s) {
                const int j = j4 * 4 + s;
                uint32_t a0[4], a1[4];
                LDSM_X4(a0, am0 + j * 32);
                LDSM_X4(a1, am1 + j * 32);
                uint32_t t0 = w0[s] >> sh0;
                uint32_t b00 = deq_nib(t0 & 0xFu);
                uint32_t b01 = deq_nib((t0 >> 16) & 0xFu);
                uint32_t t1 = w1[s] >> sh0;
                uint32_t b10 = deq_nib(t1 & 0xFu);
                uint32_t b11 = deq_nib((t1 >> 16) & 0xFu);
                MMA16816(c[0][0], a0, b00, b01);
                MMA16816(c[1][0], a1, b00, b01);
                MMA16816(c[0][1], a0, b10, b11);
                MMA16816(c[1][1], a1, b10, b11);
            }
        }

        if (cc + 1 < CPS) {
            A_STS(nb, chg + 1);
            PW_STS(nb);
        }
        BAR_SET();
    }

    // ---- reduce the two K-halves ----
    __syncthreads();          // all mma done; A region reusable as scratch

    if (set == 1) {           // set 1 publishes partials: part[m][n] fp32
#pragma unroll
        for (int mt = 0; mt < 2; ++mt) {
#pragma unroll
            for (int nt = 0; nt < 2; ++nt) {
                const int m0 = mt * 16 + (lane >> 2);
                const int n  = nbase + nt * 8 + q * 2;
                uint32_t p0 = sbase + SM_A + (uint32_t)((m0 * GS + n) * 4);
                uint32_t p1 = sbase + SM_A + (uint32_t)(((m0 + 8) * GS + n) * 4);
                asm volatile("st.shared.v2.f32 [%0], {%1, %2};"
                             :: "r"(p0), "f"(c[mt][nt][0]), "f"(c[mt][nt][1]) : "memory");
                asm volatile("st.shared.v2.f32 [%0], {%1, %2};"
                             :: "r"(p1), "f"(c[mt][nt][2]), "f"(c[mt][nt][3]) : "memory");
            }
        }
    }
    __syncthreads();

    if (set == 0) {           // set 0 adds and writes gmem
#pragma unroll
        for (int mt = 0; mt < 2; ++mt) {
#pragma unroll
            for (int nt = 0; nt < 2; ++nt) {
                const int m0 = mt * 16 + (lane >> 2);
                const int n  = nbase + nt * 8 + q * 2;
                uint32_t p0 = sbase + SM_A + (uint32_t)((m0 * GS + n) * 4);
                uint32_t p1 = sbase + SM_A + (uint32_t)(((m0 + 8) * GS + n) * 4);
                float e0, e1, e2, e3;
                asm volatile("ld.shared.v2.f32 {%0, %1}, [%2];"
                             : "=f"(e0), "=f"(e1) : "r"(p0));
                asm volatile("ld.shared.v2.f32 {%0, %1}, [%2];"
                             : "=f"(e2), "=f"(e3) : "r"(p1));
                const int col = g * GS + n;
                *reinterpret_cast<float2*>(out + (size_t)m0 * OUT_F + col) =
                    make_float2(c[mt][nt][0] + e0, c[mt][nt][1] + e1);
                *reinterpret_cast<float2*>(out + (size_t)(m0 + 8) * OUT_F + col) =
                    make_float2(c[mt][nt][2] + e2, c[mt][nt][3] + e3);
            }
        }
    }
}

extern "C" void kernel_launch(void* const* d_in, const int* in_sizes, int n_in,
                              void* d_out, int out_size) {
    // Identify inputs by element count (dtype-independent):
    //   x: 131072 ; packed: 14680064 ; scale: 458752
    const float* x  = 0;
    const int*   pw = 0;
    const float* sc = 0;
    for (int i = 0; i < n_in; ++i) {
        if      (in_sizes[i] == 131072)   x  = (const float*)d_in[i];
        else if (in_sizes[i] == 14680064) pw = (const int*)d_in[i];
        else if (in_sizes[i] == 458752)   sc = (const float*)d_in[i];
    }
    float* out = (float*)d_out;
    (void)out_size;

    cudaFuncSetAttribute(int2_linear_kernel,
                         cudaFuncAttributeMaxDynamicSharedMemorySize, SM_TOTAL);
    int2_linear_kernel<<<NGROUPS, NTHREADS, SM_TOTAL>>>(x, pw, sc, out);
}

// round 14
// speedup vs baseline: 1.5323x; 1.5323x over previous
#include <cuda_runtime.h>
#include <cuda_fp16.h>
#include <stdint.h>

// INT2 symmetric quantized linear: y[32,14336] = x[32,4096] @ W^T
//   W[o][k] = fp16(v[o][k]-2) * scale[o/128][k]  (exact in fp16: v-2 in {-2,-1,0,1})
// => y[m][o] = sum_k fp16(x[m][k]*scale[g][k]) * (v[o][k]-2)   (scale folded into A)
//
// Inputs: x f32 [131072], packed int32 [14680064] (one byte per elem), scale f32 [458752].
// 112 CTAs (one group each), 256 threads = 8 warps. K-split: warps 0-3 do K[0,2048),
// warps 4-7 do K[2048,4096); each warp owns 32 output cols. mma.sync m16n8k16,
// ldmatrix A(xs), raw-word dequant B, cp.async pw staging, f32 reduction of K-halves.

#define IN_F   4096
#define OUT_F  14336
#define GS     128
#define NGROUPS 112
#define CKR    256                  // K per chunk
#define ROUNDS 8                    // chunks per set

#define XS_STRIDE 528               // 512B fp16 + 16 pad
#define XSBUF (32 * XS_STRIDE)      // 16896
#define PWR_STRIDE 272              // 256B raw int32 + 16 pad (68 words % 32 = 4)
#define PWRBUF (128 * PWR_STRIDE)   // 34816

#define SM_SCALE 0                  // 16384 B fp32 scales
#define SM_XS    16384              // 4 bufs [set*2+parity]
#define SM_PWR   (16384 + 4 * XSBUF)        // 83968
#define SM_TOTAL (SM_PWR + 4 * PWRBUF)      // 223232
#define RED_STRIDE 132              // reduction scratch stride (floats)

__device__ __forceinline__ uint32_t smem_u32(const void* p) {
    uint32_t a;
    asm("{ .reg .u64 t; cvta.to.shared.u64 t, %1; cvt.u32.u64 %0, t; }" : "=r"(a) : "l"(p));
    return a;
}
__device__ __forceinline__ uint32_t hsub2u(uint32_t a, uint32_t b) {
    uint32_t d; asm("sub.rn.f16x2 %0, %1, %2;" : "=r"(d) : "r"(a), "r"(b)); return d;
}
// nib = two 2-bit weights (pre-masked). fp16x2 of (v0-2, v1-2), exact.
__device__ __forceinline__ uint32_t deq_nib(uint32_t nib) {
    uint32_t u = nib * 0x4001u, r;   // v0 -> bits 0-1, v1 -> bits 16-17
    asm("lop3.b32 %0, %1, %2, %3, 0xEA;" : "=r"(r)
        : "r"(u), "r"(0x00030003u), "r"(0x64006400u));
    return hsub2u(r, 0x64026402u);
}

#define LDSM_X4(R, ADDR) \
    asm volatile("ldmatrix.sync.aligned.m8n8.x4.shared.b16 {%0,%1,%2,%3}, [%4];" \
        : "=r"((R)[0]), "=r"((R)[1]), "=r"((R)[2]), "=r"((R)[3]) : "r"(ADDR))

#define MMA16816(C, A, B0, B1) \
    asm volatile("mma.sync.aligned.m16n8k16.row.col.f32.f16.f16.f32 " \
        "{%0,%1,%2,%3}, {%4,%5,%6,%7}, {%8,%9}, {%0,%1,%2,%3};" \
        : "+f"((C)[0]), "+f"((C)[1]), "+f"((C)[2]), "+f"((C)[3]) \
        : "r"((A)[0]), "r"((A)[1]), "r"((A)[2]), "r"((A)[3]), "r"(B0), "r"(B1))

#define STS128(ADDR, R0, R1, R2, R3) \
    asm volatile("st.shared.v4.b32 [%0], {%1, %2, %3, %4};" \
        :: "r"(ADDR), "r"(R0), "r"(R1), "r"(R2), "r"(R3) : "memory")

#define LDS32(DST, ADDR) \
    asm volatile("ld.shared.u32 %0, [%1];" : "=r"(DST) : "r"(ADDR))

#define LDS128F(ADDR, V) \
    asm volatile("ld.shared.v4.f32 {%0,%1,%2,%3}, [%4];" \
        : "=f"((V).x), "=f"((V).y), "=f"((V).z), "=f"((V).w) : "r"(ADDR))

#define CP_ASYNC16(SADDR, GADDR) \
    asm volatile("cp.async.cg.shared.global [%0], [%1], 16;" :: "r"(SADDR), "l"(GADDR))

__global__ void __launch_bounds__(256, 1)
int2_linear_kernel(const float* __restrict__ x,
                   const int* __restrict__ pw,     // one packed byte per int32
                   const float* __restrict__ scale,
                   float* __restrict__ out)
{
    extern __shared__ char smem[];
    const int tid  = threadIdx.x;
    const int warp = tid >> 5;
    const int lane = tid & 31;
    const int g    = blockIdx.x;
    const uint32_t sbase = smem_u32(smem);

    const int set = warp >> 2;                 // K-half this warp computes
    const int ncb = (warp & 3) * 32;           // 32 output cols per warp

    // ---- stage scales: 4096 fp32 = 16KB ----
    {
        const uint4* sg = reinterpret_cast<const uint4*>(scale + (size_t)g * IN_F);
        uint4* ss = reinterpret_cast<uint4*>(smem + SM_SCALE);
#pragma unroll
        for (int i = 0; i < 4; ++i) ss[tid + i * 256] = sg[tid + i * 256];
    }

    // ---- staging roles ----
    const int* pwg = pw + (size_t)g * GS * (IN_F / 4);   // 1024 int32 per out-row
    const int prow = tid >> 1, phalf = tid & 1;          // cp.async: 2 thr/row, 32 int32 each
    const int xrow = tid >> 3, xseg = tid & 7;           // x: 32 rows x 8 segs

    // cp.async raw pw for (s-half, chunk c) into buf (s*2 + (c&1))
#define CPW(S, C) do {                                                         \
    uint32_t dst = sbase + SM_PWR + ((S) * 2 + ((C) & 1)) * PWRBUF             \
                 + prow * PWR_STRIDE + phalf * 128;                            \
    const int* src = pwg + (size_t)prow * 1024 + (S) * 512 + (C) * 64 + phalf * 32; \
    _Pragma("unroll")                                                          \
    for (int u = 0; u < 8; ++u) CP_ASYNC16(dst + u * 16, src + u * 4);         \
} while (0)

    float4 F0[8], F1[8];   // x staging regs for set0/set1 chunks
#define XLDG(F, S, C) do {                                                     \
    const float* xg = x + (size_t)xrow * IN_F + (S) * 2048 + (C) * CKR + xseg * 8; \
    _Pragma("unroll")                                                          \
    for (int i = 0; i < 4; ++i) {                                              \
        (F)[2 * i]     = *reinterpret_cast<const float4*>(xg + i * 64);        \
        (F)[2 * i + 1] = *reinterpret_cast<const float4*>(xg + i * 64 + 4);    \
    }                                                                          \
} while (0)

#define XSTS(F, S, C) do {                                                     \
    uint32_t sa = sbase + SM_SCALE + (uint32_t)(((S) * 2048 + (C) * CKR + xseg * 8) * 4); \
    uint32_t xa = sbase + SM_XS + ((S) * 2 + ((C) & 1)) * XSBUF                \
                + xrow * XS_STRIDE + xseg * 16;                                \
    _Pragma("unroll")                                                          \
    for (int i = 0; i < 4; ++i) {                                              \
        float4 s0, s1;                                                         \
        LDS128F(sa + i * 256, s0);                                             \
        LDS128F(sa + i * 256 + 16, s1);                                        \
        float4 v0 = (F)[2 * i], v1 = (F)[2 * i + 1];                           \
        __half2 h0 = __floats2half2_rn(v0.x * s0.x, v0.y * s0.y);              \
        __half2 h1 = __floats2half2_rn(v0.z * s0.z, v0.w * s0.w);              \
        __half2 h2 = __floats2half2_rn(v1.x * s1.x, v1.y * s1.y);              \
        __half2 h3 = __floats2half2_rn(v1.z * s1.z, v1.w * s1.w);              \
        STS128(xa + i * 128,                                                   \
               *reinterpret_cast<uint32_t*>(&h0),                              \
               *reinterpret_cast<uint32_t*>(&h1),                              \
               *reinterpret_cast<uint32_t*>(&h2),                              \
               *reinterpret_cast<uint32_t*>(&h3));                             \
    }                                                                          \
} while (0)

    // ---- prologue: round 0 buffers ----
    CPW(0, 0); CPW(1, 0);
    asm volatile("cp.async.commit_group;" ::: "memory");
    XLDG(F0, 0, 0); XLDG(F1, 1, 0);
    asm volatile("cp.async.wait_group 0;" ::: "memory");
    __syncthreads();                 // scales + pw buf0 visible
    XSTS(F0, 0, 0); XSTS(F1, 1, 0);
    __syncthreads();                 // xs buf0 visible

    // ---- per-warp fragment addressing (R10-proven maps) ----
    const int q = lane & 3;
    const uint32_t sh = (uint32_t)((q & 1) * 4);      // bit shift within raw byte
    const uint32_t wsel = (uint32_t)((q >> 1) * 4);   // raw word select (k quad)
    uint32_t pkoff[4];
#pragma unroll
    for (int t = 0; t < 4; ++t)
        pkoff[t] = (uint32_t)((ncb + t * 8 + (lane >> 2)) * PWR_STRIDE) + wsel;
    const int arow = (lane & 7) + ((lane >> 3) & 1) * 8;
    const uint32_t acol = ((lane >> 4) & 1) * 16;
    const uint32_t amoff = (uint32_t)(arow * XS_STRIDE) + acol;

    float c[2][4][4] = {};    // [m-tile][n-octet][frag]

    for (int r = 0; r < ROUNDS; ++r) {
        const int par = r & 1;

        if (r + 1 < ROUNDS) {
            CPW(0, r + 1); CPW(1, r + 1);
            asm volatile("cp.async.commit_group;" ::: "memory");
            XLDG(F0, 0, r + 1); XLDG(F1, 1, r + 1);
        }

        const uint32_t pkb = sbase + SM_PWR + (set * 2 + par) * PWRBUF;
        const uint32_t am0 = sbase + SM_XS + (set * 2 + par) * XSBUF + amoff;
        const uint32_t am1 = am0 + 16 * XS_STRIDE;

#pragma unroll
        for (int j = 0; j < CKR / 16; ++j) {           // 16 ksteps
            uint32_t a0[4], a1[4];
            LDSM_X4(a0, am0 + j * 32);
            LDSM_X4(a1, am1 + j * 32);
#pragma unroll
            for (int t = 0; t < 4; ++t) {
                uint32_t r0, r1;
                LDS32(r0, pkb + pkoff[t] + j * 16);
                LDS32(r1, pkb + pkoff[t] + j * 16 + 8);
                uint32_t b0 = deq_nib((r0 >> sh) & 0xFu);
                uint32_t b1 = deq_nib((r1 >> sh) & 0xFu);
                MMA16816(c[0][t], a0, b0, b1);
                MMA16816(c[1][t], a1, b0, b1);
            }
        }

        if (r + 1 < ROUNDS) {
            XSTS(F0, 0, r + 1); XSTS(F1, 1, r + 1);
            asm volatile("cp.async.wait_group 0;" ::: "memory");
        }
        __syncthreads();
    }

    // ---- reduce K-halves (scratch reuses xs area; stride 132 floats) ----
    const uint32_t red = sbase + SM_XS;
    if (set == 1) {
#pragma unroll
        for (int mt = 0; mt < 2; ++mt) {
#pragma unroll
            for (int t = 0; t < 4; ++t) {
                const int m = mt * 16 + (lane >> 2);
                const int n = ncb + t * 8 + q * 2;
                uint32_t p0 = red + (uint32_t)((m * RED_STRIDE + n) * 4);
                uint32_t p1 = red + (uint32_t)(((m + 8) * RED_STRIDE + n) * 4);
                asm volatile("st.shared.v2.f32 [%0], {%1, %2};"
                             :: "r"(p0), "f"(c[mt][t][0]), "f"(c[mt][t][1]) : "memory");
                asm volatile("st.shared.v2.f32 [%0], {%1, %2};"
                             :: "r"(p1), "f"(c[mt][t][2]), "f"(c[mt][t][3]) : "memory");
            }
        }
    }
    __syncthreads();
    if (set == 0) {
#pragma unroll
        for (int mt = 0; mt < 2; ++mt) {
#pragma unroll
            for (int t = 0; t < 4; ++t) {
                const int m = mt * 16 + (lane >> 2);
                const int n = ncb + t * 8 + q * 2;
                uint32_t p0 = red + (uint32_t)((m * RED_STRIDE + n) * 4);
                uint32_t p1 = red + (uint32_t)(((m + 8) * RED_STRIDE + n) * 4);
                float e0, e1, e2, e3;
                asm volatile("ld.shared.v2.f32 {%0, %1}, [%2];" : "=f"(e0), "=f"(e1) : "r"(p0));
                asm volatile("ld.shared.v2.f32 {%0, %1}, [%2];" : "=f"(e2), "=f"(e3) : "r"(p1));
                const int col = g * GS + n;
                *reinterpret_cast<float2*>(out + (size_t)m * OUT_F + col) =
                    make_float2(c[mt][t][0] + e0, c[mt][t][1] + e1);
                *reinterpret_cast<float2*>(out + (size_t)(m + 8) * OUT_F + col) =
                    make_float2(c[mt][t][2] + e2, c[mt][t][3] + e3);
            }
        }
    }
}

extern "C" void kernel_launch(void* const* d_in, const int* in_sizes, int n_in,
                              void* d_out, int out_size) {
    // Identify inputs by element count: x 131072, packed 14680064, scale 458752
    const float* x  = 0;
    const int*   pw = 0;
    const float* sc = 0;
    for (int i = 0; i < n_in; ++i) {
        if      (in_sizes[i] == 131072)   x  = (const float*)d_in[i];
        else if (in_sizes[i] == 14680064) pw = (const int*)d_in[i];
        else if (in_sizes[i] == 458752)   sc = (const float*)d_in[i];
    }
    float* out = (float*)d_out;
    (void)out_size;

    cudaFuncSetAttribute(int2_linear_kernel,
                         cudaFuncAttributeMaxDynamicSharedMemorySize, SM_TOTAL);
    int2_linear_kernel<<<NGROUPS, 256, SM_TOTAL>>>(x, pw, sc, out);
}